// round 15
// baseline (speedup 1.0000x reference)
#include <cuda_runtime.h>
#include <cuda_fp16.h>
#include <cstdint>

// Problem constants
#define NN 50000
#define EE 800000
#define GG 2048
#define HH 256
#define KPAD 64   // 59 padded to 64
#define CAP 96    // fixed bucket capacity per node (E[deg]=16, P(deg>96)~1e-35)

// ---------------- device scratch (no allocation allowed) ----------------
__device__ __half g_bufA[NN * HH];     // activations ping
__device__ __half g_bufB[NN * HH];     // GEMM out
__device__ __half g_bufC[NN * HH];     // activations pong
__device__ __half g_wconv[3 * HH * HH];
__device__ __half g_wfc[3 * HH * HH];
__device__ int    g_cur[NN];           // per-node edge count
__device__ int    g_srcs[NN * CAP];    // bucketed CSR (19.2 MB)
__device__ float  g_dinv[NN];
__device__ int    g_gstart[GG + 1];
__device__ __half g_gA[GG * HH];
__device__ __half g_gB[GG * HH];

// ---------------- helpers ----------------
__device__ __forceinline__ void cp16(uint32_t dst, const void* src, uint32_t sz) {
    asm volatile("cp.async.cg.shared.global [%0], [%1], 16, %2;\n"
                 :: "r"(dst), "l"(src), "r"(sz));
}

// ---------------- bucketed CSR construction -----------------------------
__global__ void k_zero_cur() {
    int i = blockIdx.x * blockDim.x + threadIdx.x;
    if (i < NN) g_cur[i] = 0;
}
__global__ void k_scatter(const int* __restrict__ ei) {
    int e = blockIdx.x * blockDim.x + threadIdx.x;
    if (e >= EE) return;
    int s = ei[e];
    int d = ei[EE + e];
    int pos = atomicAdd(&g_cur[d], 1);
    if (pos < CAP) g_srcs[d * CAP + pos] = s;
}
__global__ void k_dinv() {
    int i = blockIdx.x * blockDim.x + threadIdx.x;
    if (i < NN) g_dinv[i] = rsqrtf((float)g_cur[i] + 1.0f);
}

// ---------------- weight conversion (fp32 -> fp16) ----------------------
__global__ void k_h16(const float* __restrict__ src, __half* __restrict__ dst,
                      int n) {
    int i = blockIdx.x * blockDim.x + threadIdx.x;
    if (i < n) dst[i] = __float2half_rn(src[i]);
}

// ---------------- fp16 mma.sync GEMM, cp.async double-buffered -----------
// C[M,256] = A[M,K] @ W[256,K]^T  (+bias)(+relu)(+rowscale)
// flags: 1=bias, 2=relu, 8=rowscale,
//        16 = A operand fp32 row-major stride 59 (K must be 64)
//        32 = W operand fp32 row-major stride 59 (K must be 64)
#define BKH 32
#define PADH 40
#define CHH (128 * PADH)

__global__ void __launch_bounds__(256, 2) gemm_f16_kernel(
    const __half* __restrict__ A, const float* __restrict__ A32,
    const __half* __restrict__ W, const float* __restrict__ W32,
    const float* __restrict__ bias, const float* __restrict__ rowscale,
    __half* __restrict__ C, int M, int K, int flags) {
    extern __shared__ __half smh[];
    __shared__ float sBias[128];

    const int tid = threadIdx.x;
    const int wid = tid >> 5;
    const int lane = tid & 31;
    const int m0 = blockIdx.x * 128;
    const int n0 = blockIdx.y * 128;
    const int warp_m = (wid >> 2) * 64;
    const int warp_n = (wid & 3) * 32;
    const bool a32 = (flags & 16) != 0;
    const bool w32 = (flags & 32) != 0;

    if (tid < 128) sBias[tid] = (flags & 1) ? bias[n0 + tid] : 0.0f;

    float acc[4][4][4];
#pragma unroll
    for (int mt = 0; mt < 4; ++mt)
#pragma unroll
        for (int nt = 0; nt < 4; ++nt)
#pragma unroll
            for (int r = 0; r < 4; ++r) acc[mt][nt][r] = 0.0f;

    const int tr = tid >> 1;
    const int tc = (tid & 1) * 16;
    const bool a_valid = (m0 + tr) < M;
    const uint32_t a_sz = a_valid ? 16u : 0u;
    const __half* arow = A + (size_t)(a_valid ? (m0 + tr) : 0) * K + tc;
    const float* a32row = A32 + (size_t)(a_valid ? (m0 + tr) : 0) * 59;
    const __half* wrow = W + (size_t)(n0 + tr) * K + tc;
    const float* w32row = W32 + (size_t)(n0 + tr) * 59;
    const uint32_t sbase = (uint32_t)__cvta_generic_to_shared(smh);
    const uint32_t sAoff = sbase + (uint32_t)(tr * PADH + tc) * 2u;

    const int lg = lane >> 2;
    const int lt = lane & 3;
    const int nch = K / BKH;

    if (!a32) {
#pragma unroll
        for (int j = 0; j < 2; ++j)
            cp16(sAoff + j * 16u, arow + j * 8, a_sz);
    }
    if (!w32) {
#pragma unroll
        for (int j = 0; j < 2; ++j)
            cp16(sAoff + CHH * 2u + j * 16u, wrow + j * 8, 16u);
    }
    asm volatile("cp.async.commit_group;\n");

    for (int c = 0; c < nch; ++c) {
        if (a32) {
            __half* dst = smh + (c & 1) * (2 * CHH) + tr * PADH + tc;
#pragma unroll
            for (int j = 0; j < 16; ++j) {
                int col = c * BKH + tc + j;
                float v = (a_valid && col < 59) ? a32row[col] : 0.0f;
                dst[j] = __float2half_rn(v);
            }
        }
        if (w32) {
            __half* dst = smh + (c & 1) * (2 * CHH) + CHH + tr * PADH + tc;
#pragma unroll
            for (int j = 0; j < 16; ++j) {
                int col = c * BKH + tc + j;
                float v = (col < 59) ? w32row[col] : 0.0f;
                dst[j] = __float2half_rn(v);
            }
        }
        if (c + 1 < nch) {
            uint32_t boff = sAoff + ((c + 1) & 1) * (2u * CHH * 2u);
            if (!a32) {
                const __half* ap = arow + (c + 1) * BKH;
#pragma unroll
                for (int j = 0; j < 2; ++j)
                    cp16(boff + j * 16u, ap + j * 8, a_sz);
            }
            if (!w32) {
                const __half* wp = wrow + (c + 1) * BKH;
#pragma unroll
                for (int j = 0; j < 2; ++j)
                    cp16(boff + CHH * 2u + j * 16u, wp + j * 8, 16u);
            }
            asm volatile("cp.async.commit_group;\n");
            asm volatile("cp.async.wait_group 1;\n");
        } else {
            asm volatile("cp.async.wait_group 0;\n");
        }
        __syncthreads();

        const __half* sA = smh + (c & 1) * (2 * CHH);
        const __half* sB = sA + CHH;
#pragma unroll
        for (int kk = 0; kk < BKH; kk += 16) {
            uint32_t afr[4][4];
            uint32_t bfr[4][2];
#pragma unroll
            for (int mt = 0; mt < 4; ++mt) {
                int ar = warp_m + mt * 16 + lg;
                afr[mt][0] = *(const uint32_t*)&sA[ar * PADH + kk + 2 * lt];
                afr[mt][1] = *(const uint32_t*)&sA[(ar + 8) * PADH + kk + 2 * lt];
                afr[mt][2] = *(const uint32_t*)&sA[ar * PADH + kk + 2 * lt + 8];
                afr[mt][3] = *(const uint32_t*)&sA[(ar + 8) * PADH + kk + 2 * lt + 8];
            }
#pragma unroll
            for (int nt = 0; nt < 4; ++nt) {
                int bn = warp_n + nt * 8 + lg;
                bfr[nt][0] = *(const uint32_t*)&sB[bn * PADH + kk + 2 * lt];
                bfr[nt][1] = *(const uint32_t*)&sB[bn * PADH + kk + 2 * lt + 8];
            }
#pragma unroll
            for (int mt = 0; mt < 4; ++mt) {
#pragma unroll
                for (int nt = 0; nt < 4; ++nt) {
                    asm volatile(
                        "mma.sync.aligned.m16n8k16.row.col.f32.f16.f16.f32 "
                        "{%0,%1,%2,%3}, {%4,%5,%6,%7}, {%8,%9}, {%0,%1,%2,%3};\n"
                        : "+f"(acc[mt][nt][0]), "+f"(acc[mt][nt][1]),
                          "+f"(acc[mt][nt][2]), "+f"(acc[mt][nt][3])
                        : "r"(afr[mt][0]), "r"(afr[mt][1]),
                          "r"(afr[mt][2]), "r"(afr[mt][3]),
                          "r"(bfr[nt][0]), "r"(bfr[nt][1]));
                }
            }
        }
        __syncthreads();
    }

    const bool do_relu = (flags & 2) != 0;
    const bool do_scale = (flags & 8) != 0;
#pragma unroll
    for (int mt = 0; mt < 4; ++mt) {
        int r0 = m0 + warp_m + mt * 16 + lg;
        int r1 = r0 + 8;
        float rs0 = 1.0f, rs1 = 1.0f;
        if (do_scale) {
            if (r0 < M) rs0 = rowscale[r0];
            if (r1 < M) rs1 = rowscale[r1];
        }
#pragma unroll
        for (int nt = 0; nt < 4; ++nt) {
            int cl = warp_n + nt * 8 + lt * 2;
            float b0 = sBias[cl], b1 = sBias[cl + 1];
            int col = n0 + cl;
            float v0 = acc[mt][nt][0] + b0;
            float v1 = acc[mt][nt][1] + b1;
            float v2 = acc[mt][nt][2] + b0;
            float v3 = acc[mt][nt][3] + b1;
            if (do_relu) {
                v0 = fmaxf(v0, 0.f); v1 = fmaxf(v1, 0.f);
                v2 = fmaxf(v2, 0.f); v3 = fmaxf(v3, 0.f);
            }
            v0 *= rs0; v1 *= rs0; v2 *= rs1; v3 *= rs1;
            if (r0 < M)
                *(__half2*)(C + (size_t)r0 * 256 + col) = __floats2half2_rn(v0, v1);
            if (r1 < M)
                *(__half2*)(C + (size_t)r1 * 256 + col) = __floats2half2_rn(v2, v3);
        }
    }
}

// ---------------- GCN aggregation: warp per node, bucketed CSR ----------
// hs = h * dinv[row] (prescaled in GEMM epilogue).
// out[node] = relu(dinv[node] * (sum_src hs[src] + hs[node]) + bias)
__global__ void aggregate_kernel(const __half* __restrict__ hs,
                                 const float* __restrict__ bias,
                                 __half* __restrict__ out) {
    int node = (blockIdx.x * blockDim.x + threadIdx.x) >> 5;
    if (node >= NN) return;
    int lane = threadIdx.x & 31;
    const int co = lane * 8;                 // 8 halves per lane
    float acc[8];
#pragma unroll
    for (int i = 0; i < 8; ++i) acc[i] = 0.0f;

    const int* bucket = &g_srcs[node * CAP];
    int cnt = g_cur[node];
    if (cnt > CAP) cnt = CAP;
    int j = 0;
    for (; j + 3 < cnt; j += 4) {
        int s0 = bucket[j], s1 = bucket[j + 1];
        int s2 = bucket[j + 2], s3 = bucket[j + 3];
        uint4 u0 = *(const uint4*)(hs + (size_t)s0 * 256 + co);
        uint4 u1 = *(const uint4*)(hs + (size_t)s1 * 256 + co);
        uint4 u2 = *(const uint4*)(hs + (size_t)s2 * 256 + co);
        uint4 u3 = *(const uint4*)(hs + (size_t)s3 * 256 + co);
        const __half2* p0 = (const __half2*)&u0;
        const __half2* p1 = (const __half2*)&u1;
        const __half2* p2 = (const __half2*)&u2;
        const __half2* p3 = (const __half2*)&u3;
#pragma unroll
        for (int q = 0; q < 4; ++q) {
            float2 f0 = __half22float2(p0[q]);
            float2 f1 = __half22float2(p1[q]);
            float2 f2 = __half22float2(p2[q]);
            float2 f3 = __half22float2(p3[q]);
            acc[q * 2 + 0] += (f0.x + f1.x) + (f2.x + f3.x);
            acc[q * 2 + 1] += (f0.y + f1.y) + (f2.y + f3.y);
        }
    }
    for (; j < cnt; ++j) {
        int s0 = bucket[j];
        uint4 u0 = *(const uint4*)(hs + (size_t)s0 * 256 + co);
        const __half2* p0 = (const __half2*)&u0;
#pragma unroll
        for (int q = 0; q < 4; ++q) {
            float2 f0 = __half22float2(p0[q]);
            acc[q * 2 + 0] += f0.x;
            acc[q * 2 + 1] += f0.y;
        }
    }

    float di = g_dinv[node];
    uint4 us = *(const uint4*)(hs + (size_t)node * 256 + co);
    const __half2* ps = (const __half2*)&us;
    float4 b0 = *(const float4*)(bias + co);
    float4 b1 = *(const float4*)(bias + co + 4);
    const float bb[8] = {b0.x, b0.y, b0.z, b0.w, b1.x, b1.y, b1.z, b1.w};
    __half2 o[4];
#pragma unroll
    for (int q = 0; q < 4; ++q) {
        float2 fs = __half22float2(ps[q]);
        float v0 = fmaxf(di * (acc[q * 2 + 0] + fs.x) + bb[q * 2 + 0], 0.0f);
        float v1 = fmaxf(di * (acc[q * 2 + 1] + fs.y) + bb[q * 2 + 1], 0.0f);
        o[q] = __floats2half2_rn(v0, v1);
    }
    *(uint4*)(out + (size_t)node * 256 + co) = *(const uint4*)o;
}

// ---------------- pooling ----------------
__global__ void k_gstart(const int* __restrict__ batch) {
    int i = blockIdx.x * blockDim.x + threadIdx.x;
    if (i >= NN) return;
    int b = batch[i];
    int prev = (i == 0) ? -1 : batch[i - 1];
    for (int g = prev + 1; g <= b; ++g) g_gstart[g] = i;
    if (i == NN - 1) {
        for (int g = b + 1; g <= GG; ++g) g_gstart[g] = NN;
    }
}
__global__ void k_pool(const __half* __restrict__ h, __half* __restrict__ out) {
    int warp = (blockIdx.x * blockDim.x + threadIdx.x) >> 5;
    if (warp >= GG) return;
    int lane = threadIdx.x & 31;
    const int co = lane * 8;
    float acc[8];
#pragma unroll
    for (int i = 0; i < 8; ++i) acc[i] = 0.0f;
    int s = g_gstart[warp], e = g_gstart[warp + 1];
    for (int i = s; i < e; ++i) {
        uint4 u = *(const uint4*)(h + (size_t)i * 256 + co);
        const __half2* p = (const __half2*)&u;
#pragma unroll
        for (int q = 0; q < 4; ++q) {
            float2 f = __half22float2(p[q]);
            acc[q * 2 + 0] += f.x;
            acc[q * 2 + 1] += f.y;
        }
    }
    __half2 o[4];
#pragma unroll
    for (int q = 0; q < 4; ++q)
        o[q] = __floats2half2_rn(acc[q * 2 + 0], acc[q * 2 + 1]);
    *(uint4*)(out + (size_t)warp * 256 + co) = *(const uint4*)o;
}

// ---------------- output head ----------------
__global__ void k_out(const __half* __restrict__ g,
                      const float* __restrict__ out_w,
                      const float* __restrict__ out_b,
                      float* __restrict__ out) {
    int warp = (blockIdx.x * blockDim.x + threadIdx.x) >> 5;
    if (warp >= GG) return;
    int lane = threadIdx.x & 31;
    const int co = lane * 8;
    uint4 u = *(const uint4*)(g + (size_t)warp * 256 + co);
    const __half2* p = (const __half2*)&u;
    float p0 = 0.f, p1 = 0.f;
#pragma unroll
    for (int q = 0; q < 4; ++q) {
        float2 f = __half22float2(p[q]);
        p0 += f.x * out_w[co + q * 2] + f.y * out_w[co + q * 2 + 1];
        p1 += f.x * out_w[256 + co + q * 2] + f.y * out_w[256 + co + q * 2 + 1];
    }
#pragma unroll
    for (int o = 16; o; o >>= 1) {
        p0 += __shfl_down_sync(0xffffffffu, p0, o);
        p1 += __shfl_down_sync(0xffffffffu, p1, o);
    }
    if (lane == 0) {
        float z0 = p0 + out_b[0];
        float z1 = p1 + out_b[1];
        float m = fmaxf(z0, z1);
        float lse = m + logf(expf(z0 - m) + expf(z1 - m));
        out[warp * 2 + 0] = z0 - lse;
        out[warp * 2 + 1] = z1 - lse;
    }
}

// ---------------- launch ----------------
extern "C" void kernel_launch(void* const* d_in, const int* in_sizes, int n_in,
                              void* d_out, int out_size) {
    const float* x       = (const float*)d_in[0];
    const int*   ei      = (const int*)d_in[1];
    const int*   batch   = (const int*)d_in[2];
    const float* W_embed = (const float*)d_in[3];
    const float* b_embed = (const float*)d_in[4];
    const float* conv_w  = (const float*)d_in[5];
    const float* conv_b  = (const float*)d_in[6];
    const float* fc_w    = (const float*)d_in[7];
    const float* fc_b    = (const float*)d_in[8];
    const float* out_w   = (const float*)d_in[9];
    const float* out_b   = (const float*)d_in[10];
    float* out = (float*)d_out;

    __half *bufA, *bufB, *bufC, *wconv, *wfc, *gA, *gB;
    float* dinv;
    cudaGetSymbolAddress((void**)&bufA, g_bufA);
    cudaGetSymbolAddress((void**)&bufB, g_bufB);
    cudaGetSymbolAddress((void**)&bufC, g_bufC);
    cudaGetSymbolAddress((void**)&wconv, g_wconv);
    cudaGetSymbolAddress((void**)&wfc, g_wfc);
    cudaGetSymbolAddress((void**)&gA, g_gA);
    cudaGetSymbolAddress((void**)&gB, g_gB);
    cudaGetSymbolAddress((void**)&dinv, g_dinv);

    static bool init_done = false;
    static cudaStream_t s2;
    static cudaEvent_t evFork, evCSR, evTail;
    if (!init_done) {
        cudaFuncSetAttribute(gemm_f16_kernel,
                             cudaFuncAttributeMaxDynamicSharedMemorySize,
                             4 * CHH * (int)sizeof(__half));
        cudaStreamCreateWithFlags(&s2, cudaStreamNonBlocking);
        cudaEventCreateWithFlags(&evFork, cudaEventDisableTiming);
        cudaEventCreateWithFlags(&evCSR, cudaEventDisableTiming);
        cudaEventCreateWithFlags(&evTail, cudaEventDisableTiming);
        init_done = true;
    }
    const int GEMM_SMEM = 4 * CHH * (int)sizeof(__half);  // 40960
    const int TB = 256;
    const int AGG_GRID = (NN * 32 + TB - 1) / TB;
    dim3 gridFull((NN + 127) / 128, 2);
    dim3 gridG((GG + 127) / 128, 2);

    cudaEventRecord(evFork, 0);
    cudaStreamWaitEvent(s2, evFork, 0);

    // ---- s2: bucketed CSR (zero -> scatter -> dinv), then tail prep ----
    k_zero_cur<<<(NN + TB - 1) / TB, TB, 0, s2>>>();
    k_scatter<<<(EE + TB - 1) / TB, TB, 0, s2>>>(ei);
    k_dinv<<<(NN + TB - 1) / TB, TB, 0, s2>>>();
    cudaEventRecord(evCSR, s2);
    k_gstart<<<(NN + TB - 1) / TB, TB, 0, s2>>>(batch);
    k_h16<<<(3 * HH * HH + TB - 1) / TB, TB, 0, s2>>>(fc_w, wfc, 3 * HH * HH);
    cudaEventRecord(evTail, s2);

    // ---- s0: conv weight convert + embed GEMM (fp32-direct A and W) ----
    k_h16<<<(3 * HH * HH + TB - 1) / TB, TB>>>(conv_w, wconv, 3 * HH * HH);
    gemm_f16_kernel<<<gridFull, 256, GEMM_SMEM>>>(
        nullptr, x, nullptr, W_embed, b_embed, nullptr, bufA,
        NN, KPAD, 3 | 16 | 32);

    cudaStreamWaitEvent(0, evCSR, 0);   // dinv + buckets needed below

    // ---- 3 conv layers, serial G->A ----
    __half* act[4] = {bufA, bufC, bufA, bufC};
    for (int i = 0; i < 3; ++i) {
        gemm_f16_kernel<<<gridFull, 256, GEMM_SMEM>>>(
            act[i], nullptr, wconv + (size_t)i * HH * HH, nullptr, nullptr,
            dinv, bufB, NN, HH, 8);
        aggregate_kernel<<<AGG_GRID, TB>>>(bufB, conv_b + (size_t)i * HH,
                                           act[i + 1]);
    }

    // ---- tail: pool + FC stack + output ----
    cudaStreamWaitEvent(0, evTail, 0);
    k_pool<<<(GG * 32) / TB, TB>>>(bufC, gA);
    gemm_f16_kernel<<<gridG, 256, GEMM_SMEM>>>(gA, nullptr, wfc, nullptr,
                                               fc_b, nullptr, gB, GG, HH, 3);
    gemm_f16_kernel<<<gridG, 256, GEMM_SMEM>>>(gB, nullptr, wfc + HH * HH,
                                               nullptr, fc_b + HH, nullptr,
                                               gA, GG, HH, 3);
    gemm_f16_kernel<<<gridG, 256, GEMM_SMEM>>>(gA, nullptr, wfc + 2 * HH * HH,
                                               nullptr, fc_b + 2 * HH, nullptr,
                                               gB, GG, HH, 3);
    k_out<<<(GG * 32) / TB, TB>>>(gB, out_w, out_b, out);
}

// round 16
// speedup vs baseline: 1.0055x; 1.0055x over previous
#include <cuda_runtime.h>
#include <cuda_fp16.h>
#include <cstdint>

// Problem constants
#define NN 50000
#define EE 800000
#define GG 2048
#define HH 256
#define KPAD 64   // 59 padded to 64

#define SCAN_B 1024
#define SCAN_NB ((NN + SCAN_B - 1) / SCAN_B)   // 49

// ---------------- device scratch (no allocation allowed) ----------------
__device__ __half g_bufA[NN * HH];     // activations ping
__device__ __half g_bufB[NN * HH];     // GEMM out
__device__ __half g_bufC[NN * HH];     // activations pong
__device__ __half g_wconv[3 * HH * HH];
__device__ __half g_wfc[3 * HH * HH];
__device__ int    g_deg[NN];
__device__ int    g_off[NN + 1];
__device__ int    g_cur[NN];
__device__ int    g_bsum[SCAN_NB];
__device__ int    g_srcs[EE];
__device__ float  g_dinv[NN];
__device__ int    g_gstart[GG + 1];
__device__ __half g_gA[GG * HH];
__device__ __half g_gB[GG * HH];

// ---------------- helpers ----------------
__device__ __forceinline__ void cp16(uint32_t dst, const void* src, uint32_t sz) {
    asm volatile("cp.async.cg.shared.global [%0], [%1], 16, %2;\n"
                 :: "r"(dst), "l"(src), "r"(sz));
}

// ---------------- CSR construction ----------------
__global__ void k_zero_deg() {
    int i = blockIdx.x * blockDim.x + threadIdx.x;
    if (i < NN) g_deg[i] = 0;
}
__global__ void k_hist(const int* __restrict__ ei) {
    int e = blockIdx.x * blockDim.x + threadIdx.x;
    if (e < EE) atomicAdd(&g_deg[ei[EE + e]], 1);
}
// scan stage 1 + dinv (reads deg anyway)
__global__ void __launch_bounds__(SCAN_B) k_scan1() {
    __shared__ int ws[32];
    __shared__ int we[32];
    const int t = threadIdx.x;
    const int lane = t & 31;
    const int wid = t >> 5;
    const int idx = blockIdx.x * SCAN_B + t;
    int v = (idx < NN) ? g_deg[idx] : 0;
    if (idx < NN) g_dinv[idx] = rsqrtf((float)v + 1.0f);
    int incl = v;
#pragma unroll
    for (int o = 1; o < 32; o <<= 1) {
        int u = __shfl_up_sync(0xffffffffu, incl, o);
        if (lane >= o) incl += u;
    }
    if (lane == 31) ws[wid] = incl;
    __syncthreads();
    if (wid == 0) {
        int s = ws[lane];
        int iv = s;
#pragma unroll
        for (int o = 1; o < 32; o <<= 1) {
            int u = __shfl_up_sync(0xffffffffu, iv, o);
            if (lane >= o) iv += u;
        }
        we[lane] = iv - s;
    }
    __syncthreads();
    int excl = we[wid] + incl - v;
    if (idx < NN) g_off[idx] = excl;
    if (t == SCAN_B - 1) g_bsum[blockIdx.x] = excl + v;
}
// fused scan stages 2+3: each block derives its base from g_bsum directly
__global__ void __launch_bounds__(SCAN_B) k_scan3() {
    __shared__ int sb[SCAN_NB];
    __shared__ int s_base;
    const int t = threadIdx.x;
    if (t < SCAN_NB) sb[t] = g_bsum[t];
    __syncthreads();
    if (t == 0) {
        int base = 0;
        for (int i = 0; i < (int)blockIdx.x; ++i) base += sb[i];
        s_base = base;
        if (blockIdx.x == 0) {
            int tot = 0;
#pragma unroll
            for (int i = 0; i < SCAN_NB; ++i) tot += sb[i];
            g_off[NN] = tot;
        }
    }
    __syncthreads();
    int idx = blockIdx.x * SCAN_B + t;
    if (idx < NN) {
        int v = g_off[idx] + s_base;
        g_off[idx] = v;
        g_cur[idx] = v;
    }
}
__global__ void k_scatter(const int* __restrict__ ei) {
    int e = blockIdx.x * blockDim.x + threadIdx.x;
    if (e >= EE) return;
    int s = ei[e];
    int d = ei[EE + e];
    int pos = atomicAdd(&g_cur[d], 1);
    g_srcs[pos] = s;
}

// ---------------- weight conversion (fp32 -> fp16) ----------------------
__global__ void k_h16(const float* __restrict__ src, __half* __restrict__ dst,
                      int n) {
    int i = blockIdx.x * blockDim.x + threadIdx.x;
    if (i < n) dst[i] = __float2half_rn(src[i]);
}

// ---------------- fp16 mma.sync GEMM, cp.async double-buffered -----------
// C[M,256] = A[M,K] @ W[256,K]^T  (+bias)(+relu)(+rowscale)
// flags: 1=bias, 2=relu, 8=rowscale,
//        16 = A operand fp32 row-major stride 59 (K must be 64)
//        32 = W operand fp32 row-major stride 59 (K must be 64)
#define BKH 32
#define PADH 40
#define CHH (128 * PADH)

__global__ void __launch_bounds__(256, 2) gemm_f16_kernel(
    const __half* __restrict__ A, const float* __restrict__ A32,
    const __half* __restrict__ W, const float* __restrict__ W32,
    const float* __restrict__ bias, const float* __restrict__ rowscale,
    __half* __restrict__ C, int M, int K, int flags) {
    extern __shared__ __half smh[];
    __shared__ float sBias[128];

    const int tid = threadIdx.x;
    const int wid = tid >> 5;
    const int lane = tid & 31;
    const int m0 = blockIdx.x * 128;
    const int n0 = blockIdx.y * 128;
    const int warp_m = (wid >> 2) * 64;
    const int warp_n = (wid & 3) * 32;
    const bool a32 = (flags & 16) != 0;
    const bool w32 = (flags & 32) != 0;

    if (tid < 128) sBias[tid] = (flags & 1) ? bias[n0 + tid] : 0.0f;

    float acc[4][4][4];
#pragma unroll
    for (int mt = 0; mt < 4; ++mt)
#pragma unroll
        for (int nt = 0; nt < 4; ++nt)
#pragma unroll
            for (int r = 0; r < 4; ++r) acc[mt][nt][r] = 0.0f;

    const int tr = tid >> 1;
    const int tc = (tid & 1) * 16;
    const bool a_valid = (m0 + tr) < M;
    const uint32_t a_sz = a_valid ? 16u : 0u;
    const __half* arow = A + (size_t)(a_valid ? (m0 + tr) : 0) * K + tc;
    const float* a32row = A32 + (size_t)(a_valid ? (m0 + tr) : 0) * 59;
    const __half* wrow = W + (size_t)(n0 + tr) * K + tc;
    const float* w32row = W32 + (size_t)(n0 + tr) * 59;
    const uint32_t sbase = (uint32_t)__cvta_generic_to_shared(smh);
    const uint32_t sAoff = sbase + (uint32_t)(tr * PADH + tc) * 2u;

    const int lg = lane >> 2;
    const int lt = lane & 3;
    const int nch = K / BKH;

    if (!a32) {
#pragma unroll
        for (int j = 0; j < 2; ++j)
            cp16(sAoff + j * 16u, arow + j * 8, a_sz);
    }
    if (!w32) {
#pragma unroll
        for (int j = 0; j < 2; ++j)
            cp16(sAoff + CHH * 2u + j * 16u, wrow + j * 8, 16u);
    }
    asm volatile("cp.async.commit_group;\n");

    for (int c = 0; c < nch; ++c) {
        if (a32) {
            __half* dst = smh + (c & 1) * (2 * CHH) + tr * PADH + tc;
#pragma unroll
            for (int j = 0; j < 16; ++j) {
                int col = c * BKH + tc + j;
                float v = (a_valid && col < 59) ? a32row[col] : 0.0f;
                dst[j] = __float2half_rn(v);
            }
        }
        if (w32) {
            __half* dst = smh + (c & 1) * (2 * CHH) + CHH + tr * PADH + tc;
#pragma unroll
            for (int j = 0; j < 16; ++j) {
                int col = c * BKH + tc + j;
                float v = (col < 59) ? w32row[col] : 0.0f;
                dst[j] = __float2half_rn(v);
            }
        }
        if (c + 1 < nch) {
            uint32_t boff = sAoff + ((c + 1) & 1) * (2u * CHH * 2u);
            if (!a32) {
                const __half* ap = arow + (c + 1) * BKH;
#pragma unroll
                for (int j = 0; j < 2; ++j)
                    cp16(boff + j * 16u, ap + j * 8, a_sz);
            }
            if (!w32) {
                const __half* wp = wrow + (c + 1) * BKH;
#pragma unroll
                for (int j = 0; j < 2; ++j)
                    cp16(boff + CHH * 2u + j * 16u, wp + j * 8, 16u);
            }
            asm volatile("cp.async.commit_group;\n");
            asm volatile("cp.async.wait_group 1;\n");
        } else {
            asm volatile("cp.async.wait_group 0;\n");
        }
        __syncthreads();

        const __half* sA = smh + (c & 1) * (2 * CHH);
        const __half* sB = sA + CHH;
#pragma unroll
        for (int kk = 0; kk < BKH; kk += 16) {
            uint32_t afr[4][4];
            uint32_t bfr[4][2];
#pragma unroll
            for (int mt = 0; mt < 4; ++mt) {
                int ar = warp_m + mt * 16 + lg;
                afr[mt][0] = *(const uint32_t*)&sA[ar * PADH + kk + 2 * lt];
                afr[mt][1] = *(const uint32_t*)&sA[(ar + 8) * PADH + kk + 2 * lt];
                afr[mt][2] = *(const uint32_t*)&sA[ar * PADH + kk + 2 * lt + 8];
                afr[mt][3] = *(const uint32_t*)&sA[(ar + 8) * PADH + kk + 2 * lt + 8];
            }
#pragma unroll
            for (int nt = 0; nt < 4; ++nt) {
                int bn = warp_n + nt * 8 + lg;
                bfr[nt][0] = *(const uint32_t*)&sB[bn * PADH + kk + 2 * lt];
                bfr[nt][1] = *(const uint32_t*)&sB[bn * PADH + kk + 2 * lt + 8];
            }
#pragma unroll
            for (int mt = 0; mt < 4; ++mt) {
#pragma unroll
                for (int nt = 0; nt < 4; ++nt) {
                    asm volatile(
                        "mma.sync.aligned.m16n8k16.row.col.f32.f16.f16.f32 "
                        "{%0,%1,%2,%3}, {%4,%5,%6,%7}, {%8,%9}, {%0,%1,%2,%3};\n"
                        : "+f"(acc[mt][nt][0]), "+f"(acc[mt][nt][1]),
                          "+f"(acc[mt][nt][2]), "+f"(acc[mt][nt][3])
                        : "r"(afr[mt][0]), "r"(afr[mt][1]),
                          "r"(afr[mt][2]), "r"(afr[mt][3]),
                          "r"(bfr[nt][0]), "r"(bfr[nt][1]));
                }
            }
        }
        __syncthreads();
    }

    const bool do_relu = (flags & 2) != 0;
    const bool do_scale = (flags & 8) != 0;
#pragma unroll
    for (int mt = 0; mt < 4; ++mt) {
        int r0 = m0 + warp_m + mt * 16 + lg;
        int r1 = r0 + 8;
        float rs0 = 1.0f, rs1 = 1.0f;
        if (do_scale) {
            if (r0 < M) rs0 = rowscale[r0];
            if (r1 < M) rs1 = rowscale[r1];
        }
#pragma unroll
        for (int nt = 0; nt < 4; ++nt) {
            int cl = warp_n + nt * 8 + lt * 2;
            float b0 = sBias[cl], b1 = sBias[cl + 1];
            int col = n0 + cl;
            float v0 = acc[mt][nt][0] + b0;
            float v1 = acc[mt][nt][1] + b1;
            float v2 = acc[mt][nt][2] + b0;
            float v3 = acc[mt][nt][3] + b1;
            if (do_relu) {
                v0 = fmaxf(v0, 0.f); v1 = fmaxf(v1, 0.f);
                v2 = fmaxf(v2, 0.f); v3 = fmaxf(v3, 0.f);
            }
            v0 *= rs0; v1 *= rs0; v2 *= rs1; v3 *= rs1;
            if (r0 < M)
                *(__half2*)(C + (size_t)r0 * 256 + col) = __floats2half2_rn(v0, v1);
            if (r1 < M)
                *(__half2*)(C + (size_t)r1 * 256 + col) = __floats2half2_rn(v2, v3);
        }
    }
}

// ---------------- GCN aggregation: warp per node, x4 unroll -------------
// hs = h * dinv[row] (prescaled in GEMM epilogue).
// out[node] = relu(dinv[node] * (sum_src hs[src] + hs[node]) + bias)
__global__ void aggregate_kernel(const __half* __restrict__ hs,
                                 const float* __restrict__ bias,
                                 __half* __restrict__ out) {
    int node = (blockIdx.x * blockDim.x + threadIdx.x) >> 5;
    if (node >= NN) return;
    int lane = threadIdx.x & 31;
    const int co = lane * 8;                 // 8 halves per lane
    float acc[8];
#pragma unroll
    for (int i = 0; i < 8; ++i) acc[i] = 0.0f;

    int s = g_off[node], e = g_off[node + 1];
    int j = s;
    for (; j + 3 < e; j += 4) {
        int s0 = g_srcs[j], s1 = g_srcs[j + 1];
        int s2 = g_srcs[j + 2], s3 = g_srcs[j + 3];
        uint4 u0 = *(const uint4*)(hs + (size_t)s0 * 256 + co);
        uint4 u1 = *(const uint4*)(hs + (size_t)s1 * 256 + co);
        uint4 u2 = *(const uint4*)(hs + (size_t)s2 * 256 + co);
        uint4 u3 = *(const uint4*)(hs + (size_t)s3 * 256 + co);
        const __half2* p0 = (const __half2*)&u0;
        const __half2* p1 = (const __half2*)&u1;
        const __half2* p2 = (const __half2*)&u2;
        const __half2* p3 = (const __half2*)&u3;
#pragma unroll
        for (int q = 0; q < 4; ++q) {
            float2 f0 = __half22float2(p0[q]);
            float2 f1 = __half22float2(p1[q]);
            float2 f2 = __half22float2(p2[q]);
            float2 f3 = __half22float2(p3[q]);
            acc[q * 2 + 0] += (f0.x + f1.x) + (f2.x + f3.x);
            acc[q * 2 + 1] += (f0.y + f1.y) + (f2.y + f3.y);
        }
    }
    for (; j < e; ++j) {
        int s0 = g_srcs[j];
        uint4 u0 = *(const uint4*)(hs + (size_t)s0 * 256 + co);
        const __half2* p0 = (const __half2*)&u0;
#pragma unroll
        for (int q = 0; q < 4; ++q) {
            float2 f0 = __half22float2(p0[q]);
            acc[q * 2 + 0] += f0.x;
            acc[q * 2 + 1] += f0.y;
        }
    }

    float di = g_dinv[node];
    uint4 us = *(const uint4*)(hs + (size_t)node * 256 + co);
    const __half2* ps = (const __half2*)&us;
    float4 b0 = *(const float4*)(bias + co);
    float4 b1 = *(const float4*)(bias + co + 4);
    const float bb[8] = {b0.x, b0.y, b0.z, b0.w, b1.x, b1.y, b1.z, b1.w};
    __half2 o[4];
#pragma unroll
    for (int q = 0; q < 4; ++q) {
        float2 fs = __half22float2(ps[q]);
        float v0 = fmaxf(di * (acc[q * 2 + 0] + fs.x) + bb[q * 2 + 0], 0.0f);
        float v1 = fmaxf(di * (acc[q * 2 + 1] + fs.y) + bb[q * 2 + 1], 0.0f);
        o[q] = __floats2half2_rn(v0, v1);
    }
    *(uint4*)(out + (size_t)node * 256 + co) = *(const uint4*)o;
}

// ---------------- pooling ----------------
__global__ void k_gstart(const int* __restrict__ batch) {
    int i = blockIdx.x * blockDim.x + threadIdx.x;
    if (i >= NN) return;
    int b = batch[i];
    int prev = (i == 0) ? -1 : batch[i - 1];
    for (int g = prev + 1; g <= b; ++g) g_gstart[g] = i;
    if (i == NN - 1) {
        for (int g = b + 1; g <= GG; ++g) g_gstart[g] = NN;
    }
}
__global__ void k_pool(const __half* __restrict__ h, __half* __restrict__ out) {
    int warp = (blockIdx.x * blockDim.x + threadIdx.x) >> 5;
    if (warp >= GG) return;
    int lane = threadIdx.x & 31;
    const int co = lane * 8;
    float acc[8];
#pragma unroll
    for (int i = 0; i < 8; ++i) acc[i] = 0.0f;
    int s = g_gstart[warp], e = g_gstart[warp + 1];
    for (int i = s; i < e; ++i) {
        uint4 u = *(const uint4*)(h + (size_t)i * 256 + co);
        const __half2* p = (const __half2*)&u;
#pragma unroll
        for (int q = 0; q < 4; ++q) {
            float2 f = __half22float2(p[q]);
            acc[q * 2 + 0] += f.x;
            acc[q * 2 + 1] += f.y;
        }
    }
    __half2 o[4];
#pragma unroll
    for (int q = 0; q < 4; ++q)
        o[q] = __floats2half2_rn(acc[q * 2 + 0], acc[q * 2 + 1]);
    *(uint4*)(out + (size_t)warp * 256 + co) = *(const uint4*)o;
}

// ---------------- output head ----------------
__global__ void k_out(const __half* __restrict__ g,
                      const float* __restrict__ out_w,
                      const float* __restrict__ out_b,
                      float* __restrict__ out) {
    int warp = (blockIdx.x * blockDim.x + threadIdx.x) >> 5;
    if (warp >= GG) return;
    int lane = threadIdx.x & 31;
    const int co = lane * 8;
    uint4 u = *(const uint4*)(g + (size_t)warp * 256 + co);
    const __half2* p = (const __half2*)&u;
    float p0 = 0.f, p1 = 0.f;
#pragma unroll
    for (int q = 0; q < 4; ++q) {
        float2 f = __half22float2(p[q]);
        p0 += f.x * out_w[co + q * 2] + f.y * out_w[co + q * 2 + 1];
        p1 += f.x * out_w[256 + co + q * 2] + f.y * out_w[256 + co + q * 2 + 1];
    }
#pragma unroll
    for (int o = 16; o; o >>= 1) {
        p0 += __shfl_down_sync(0xffffffffu, p0, o);
        p1 += __shfl_down_sync(0xffffffffu, p1, o);
    }
    if (lane == 0) {
        float z0 = p0 + out_b[0];
        float z1 = p1 + out_b[1];
        float m = fmaxf(z0, z1);
        float lse = m + logf(expf(z0 - m) + expf(z1 - m));
        out[warp * 2 + 0] = z0 - lse;
        out[warp * 2 + 1] = z1 - lse;
    }
}

// ---------------- launch ----------------
extern "C" void kernel_launch(void* const* d_in, const int* in_sizes, int n_in,
                              void* d_out, int out_size) {
    const float* x       = (const float*)d_in[0];
    const int*   ei      = (const int*)d_in[1];
    const int*   batch   = (const int*)d_in[2];
    const float* W_embed = (const float*)d_in[3];
    const float* b_embed = (const float*)d_in[4];
    const float* conv_w  = (const float*)d_in[5];
    const float* conv_b  = (const float*)d_in[6];
    const float* fc_w    = (const float*)d_in[7];
    const float* fc_b    = (const float*)d_in[8];
    const float* out_w   = (const float*)d_in[9];
    const float* out_b   = (const float*)d_in[10];
    float* out = (float*)d_out;

    __half *bufA, *bufB, *bufC, *wconv, *wfc, *gA, *gB;
    float* dinv;
    cudaGetSymbolAddress((void**)&bufA, g_bufA);
    cudaGetSymbolAddress((void**)&bufB, g_bufB);
    cudaGetSymbolAddress((void**)&bufC, g_bufC);
    cudaGetSymbolAddress((void**)&wconv, g_wconv);
    cudaGetSymbolAddress((void**)&wfc, g_wfc);
    cudaGetSymbolAddress((void**)&gA, g_gA);
    cudaGetSymbolAddress((void**)&gB, g_gB);
    cudaGetSymbolAddress((void**)&dinv, g_dinv);

    static bool init_done = false;
    static cudaStream_t s2;
    static cudaEvent_t evFork, evDinv, evCSR, evTail;
    if (!init_done) {
        cudaFuncSetAttribute(gemm_f16_kernel,
                             cudaFuncAttributeMaxDynamicSharedMemorySize,
                             4 * CHH * (int)sizeof(__half));
        cudaStreamCreateWithFlags(&s2, cudaStreamNonBlocking);
        cudaEventCreateWithFlags(&evFork, cudaEventDisableTiming);
        cudaEventCreateWithFlags(&evDinv, cudaEventDisableTiming);
        cudaEventCreateWithFlags(&evCSR, cudaEventDisableTiming);
        cudaEventCreateWithFlags(&evTail, cudaEventDisableTiming);
        init_done = true;
    }
    const int GEMM_SMEM = 4 * CHH * (int)sizeof(__half);  // 40960
    const int TB = 256;
    const int AGG_GRID = (NN * 32 + TB - 1) / TB;
    dim3 gridFull((NN + 127) / 128, 2);
    dim3 gridG((GG + 127) / 128, 2);

    cudaEventRecord(evFork, 0);
    cudaStreamWaitEvent(s2, evFork, 0);

    // ---- s2: CSR chain; evCSR fires right after scatter ----
    k_zero_deg<<<(NN + TB - 1) / TB, TB, 0, s2>>>();
    k_hist<<<(EE + TB - 1) / TB, TB, 0, s2>>>(ei);
    k_scan1<<<SCAN_NB, SCAN_B, 0, s2>>>();
    cudaEventRecord(evDinv, s2);
    k_scan3<<<SCAN_NB, SCAN_B, 0, s2>>>();
    k_scatter<<<(EE + TB - 1) / TB, TB, 0, s2>>>(ei);
    cudaEventRecord(evCSR, s2);
    // tail prep stays on s2, off the aggregate critical path
    k_gstart<<<(NN + TB - 1) / TB, TB, 0, s2>>>(batch);
    k_h16<<<(3 * HH * HH + TB - 1) / TB, TB, 0, s2>>>(fc_w, wfc, 3 * HH * HH);
    cudaEventRecord(evTail, s2);

    // ---- s0: conv weight convert + embed GEMM + conv1 GEMM ----
    k_h16<<<(3 * HH * HH + TB - 1) / TB, TB>>>(conv_w, wconv, 3 * HH * HH);
    gemm_f16_kernel<<<gridFull, 256, GEMM_SMEM>>>(
        nullptr, x, nullptr, W_embed, b_embed, nullptr, bufA,
        NN, KPAD, 3 | 16 | 32);
    cudaStreamWaitEvent(0, evDinv, 0);   // conv1 rowscale needs dinv
    gemm_f16_kernel<<<gridFull, 256, GEMM_SMEM>>>(
        bufA, nullptr, wconv, nullptr, nullptr, dinv, bufB, NN, HH, 8);

    cudaStreamWaitEvent(0, evCSR, 0);    // aggregates need off/srcs

    // ---- conv layers (conv1 GEMM already issued) ----
    __half* act[4] = {bufA, bufC, bufA, bufC};
    aggregate_kernel<<<AGG_GRID, TB>>>(bufB, conv_b, act[1]);
    for (int i = 1; i < 3; ++i) {
        gemm_f16_kernel<<<gridFull, 256, GEMM_SMEM>>>(
            act[i], nullptr, wconv + (size_t)i * HH * HH, nullptr, nullptr,
            dinv, bufB, NN, HH, 8);
        aggregate_kernel<<<AGG_GRID, TB>>>(bufB, conv_b + (size_t)i * HH,
                                           act[i + 1]);
    }

    // ---- tail: pool + FC stack + output ----
    cudaStreamWaitEvent(0, evTail, 0);
    k_pool<<<(GG * 32) / TB, TB>>>(bufC, gA);
    gemm_f16_kernel<<<gridG, 256, GEMM_SMEM>>>(gA, nullptr, wfc, nullptr,
                                               fc_b, nullptr, gB, GG, HH, 3);
    gemm_f16_kernel<<<gridG, 256, GEMM_SMEM>>>(gB, nullptr, wfc + HH * HH,
                                               nullptr, fc_b + HH, nullptr,
                                               gA, GG, HH, 3);
    gemm_f16_kernel<<<gridG, 256, GEMM_SMEM>>>(gA, nullptr, wfc + 2 * HH * HH,
                                               nullptr, fc_b + 2 * HH, nullptr,
                                               gB, GG, HH, 3);
    k_out<<<(GG * 32) / TB, TB>>>(gB, out_w, out_b, out);
}

// round 17
// speedup vs baseline: 1.0346x; 1.0289x over previous
#include <cuda_runtime.h>
#include <cuda_fp16.h>
#include <cstdint>

// Problem constants
#define NN 50000
#define EE 800000
#define GG 2048
#define HH 256
#define KPAD 64   // 59 padded to 64

#define SCAN_B 1024
#define SCAN_NB ((NN + SCAN_B - 1) / SCAN_B)   // 49

// ---------------- device scratch (no allocation allowed) ----------------
__device__ __half g_bufA[NN * HH];     // activations ping
__device__ __half g_bufB[NN * HH];     // GEMM out
__device__ __half g_bufC[NN * HH];     // activations pong
__device__ __half g_wconv[3 * HH * HH];
__device__ __half g_wfc[3 * HH * HH];
__device__ int    g_deg[NN];
__device__ int    g_off[NN + 1];
__device__ int    g_cur[NN];
__device__ int    g_bsum[SCAN_NB];
__device__ int    g_srcs[EE];
__device__ float  g_dinv[NN];
__device__ int    g_gstart[GG + 1];
__device__ __half g_gA[GG * HH];
__device__ __half g_gB[GG * HH];

// ---------------- helpers ----------------
__device__ __forceinline__ void cp16(uint32_t dst, const void* src, uint32_t sz) {
    asm volatile("cp.async.cg.shared.global [%0], [%1], 16, %2;\n"
                 :: "r"(dst), "l"(src), "r"(sz));
}

// ---------------- CSR construction ----------------
__global__ void k_zero_deg() {
    int i = blockIdx.x * blockDim.x + threadIdx.x;
    if (i < NN) g_deg[i] = 0;
}
__global__ void k_hist(const int* __restrict__ ei) {
    int e = blockIdx.x * blockDim.x + threadIdx.x;
    if (e < EE) atomicAdd(&g_deg[ei[EE + e]], 1);
}
// scan stage 1 + dinv (reads deg anyway)
__global__ void __launch_bounds__(SCAN_B) k_scan1() {
    __shared__ int ws[32];
    __shared__ int we[32];
    const int t = threadIdx.x;
    const int lane = t & 31;
    const int wid = t >> 5;
    const int idx = blockIdx.x * SCAN_B + t;
    int v = (idx < NN) ? g_deg[idx] : 0;
    if (idx < NN) g_dinv[idx] = rsqrtf((float)v + 1.0f);
    int incl = v;
#pragma unroll
    for (int o = 1; o < 32; o <<= 1) {
        int u = __shfl_up_sync(0xffffffffu, incl, o);
        if (lane >= o) incl += u;
    }
    if (lane == 31) ws[wid] = incl;
    __syncthreads();
    if (wid == 0) {
        int s = ws[lane];
        int iv = s;
#pragma unroll
        for (int o = 1; o < 32; o <<= 1) {
            int u = __shfl_up_sync(0xffffffffu, iv, o);
            if (lane >= o) iv += u;
        }
        we[lane] = iv - s;
    }
    __syncthreads();
    int excl = we[wid] + incl - v;
    if (idx < NN) g_off[idx] = excl;
    if (t == SCAN_B - 1) g_bsum[blockIdx.x] = excl + v;
}
// fused scan stages 2+3: each block derives its base from g_bsum directly
__global__ void __launch_bounds__(SCAN_B) k_scan3() {
    __shared__ int sb[SCAN_NB];
    __shared__ int s_base;
    const int t = threadIdx.x;
    if (t < SCAN_NB) sb[t] = g_bsum[t];
    __syncthreads();
    if (t == 0) {
        int base = 0;
        for (int i = 0; i < (int)blockIdx.x; ++i) base += sb[i];
        s_base = base;
        if (blockIdx.x == 0) {
            int tot = 0;
#pragma unroll
            for (int i = 0; i < SCAN_NB; ++i) tot += sb[i];
            g_off[NN] = tot;
        }
    }
    __syncthreads();
    int idx = blockIdx.x * SCAN_B + t;
    if (idx < NN) {
        int v = g_off[idx] + s_base;
        g_off[idx] = v;
        g_cur[idx] = v;
    }
}
__global__ void k_scatter(const int* __restrict__ ei) {
    int e = blockIdx.x * blockDim.x + threadIdx.x;
    if (e >= EE) return;
    int s = ei[e];
    int d = ei[EE + e];
    int pos = atomicAdd(&g_cur[d], 1);
    g_srcs[pos] = s;
}

// ---------------- weight conversion (fp32 -> fp16) ----------------------
__global__ void k_h16(const float* __restrict__ src, __half* __restrict__ dst,
                      int n) {
    int i = blockIdx.x * blockDim.x + threadIdx.x;
    if (i < n) dst[i] = __float2half_rn(src[i]);
}

// ---------------- fp16 mma.sync GEMM, cp.async double-buffered -----------
// C[M,256] = A[M,K] @ W[256,K]^T  (+bias)(+relu)(+rowscale)
// flags: 1=bias, 2=relu, 8=rowscale,
//        16 = A operand fp32 row-major stride 59 (K must be 64)
//        32 = W operand fp32 row-major stride 59 (K must be 64)
#define BKH 32
#define PADH 40
#define CHH (128 * PADH)

__global__ void __launch_bounds__(256, 2) gemm_f16_kernel(
    const __half* __restrict__ A, const float* __restrict__ A32,
    const __half* __restrict__ W, const float* __restrict__ W32,
    const float* __restrict__ bias, const float* __restrict__ rowscale,
    __half* __restrict__ C, int M, int K, int flags) {
    extern __shared__ __half smh[];
    __shared__ float sBias[128];

    const int tid = threadIdx.x;
    const int wid = tid >> 5;
    const int lane = tid & 31;
    const int m0 = blockIdx.x * 128;
    const int n0 = blockIdx.y * 128;
    const int warp_m = (wid >> 2) * 64;
    const int warp_n = (wid & 3) * 32;
    const bool a32 = (flags & 16) != 0;
    const bool w32 = (flags & 32) != 0;

    if (tid < 128) sBias[tid] = (flags & 1) ? bias[n0 + tid] : 0.0f;

    float acc[4][4][4];
#pragma unroll
    for (int mt = 0; mt < 4; ++mt)
#pragma unroll
        for (int nt = 0; nt < 4; ++nt)
#pragma unroll
            for (int r = 0; r < 4; ++r) acc[mt][nt][r] = 0.0f;

    const int tr = tid >> 1;
    const int tc = (tid & 1) * 16;
    const bool a_valid = (m0 + tr) < M;
    const uint32_t a_sz = a_valid ? 16u : 0u;
    const __half* arow = A + (size_t)(a_valid ? (m0 + tr) : 0) * K + tc;
    const float* a32row = A32 + (size_t)(a_valid ? (m0 + tr) : 0) * 59;
    const __half* wrow = W + (size_t)(n0 + tr) * K + tc;
    const float* w32row = W32 + (size_t)(n0 + tr) * 59;
    const uint32_t sbase = (uint32_t)__cvta_generic_to_shared(smh);
    const uint32_t sAoff = sbase + (uint32_t)(tr * PADH + tc) * 2u;

    const int lg = lane >> 2;
    const int lt = lane & 3;
    const int nch = K / BKH;

    if (!a32) {
#pragma unroll
        for (int j = 0; j < 2; ++j)
            cp16(sAoff + j * 16u, arow + j * 8, a_sz);
    }
    if (!w32) {
#pragma unroll
        for (int j = 0; j < 2; ++j)
            cp16(sAoff + CHH * 2u + j * 16u, wrow + j * 8, 16u);
    }
    asm volatile("cp.async.commit_group;\n");

    for (int c = 0; c < nch; ++c) {
        if (a32) {
            __half* dst = smh + (c & 1) * (2 * CHH) + tr * PADH + tc;
#pragma unroll
            for (int j = 0; j < 16; ++j) {
                int col = c * BKH + tc + j;
                float v = (a_valid && col < 59) ? a32row[col] : 0.0f;
                dst[j] = __float2half_rn(v);
            }
        }
        if (w32) {
            __half* dst = smh + (c & 1) * (2 * CHH) + CHH + tr * PADH + tc;
#pragma unroll
            for (int j = 0; j < 16; ++j) {
                int col = c * BKH + tc + j;
                float v = (col < 59) ? w32row[col] : 0.0f;
                dst[j] = __float2half_rn(v);
            }
        }
        if (c + 1 < nch) {
            uint32_t boff = sAoff + ((c + 1) & 1) * (2u * CHH * 2u);
            if (!a32) {
                const __half* ap = arow + (c + 1) * BKH;
#pragma unroll
                for (int j = 0; j < 2; ++j)
                    cp16(boff + j * 16u, ap + j * 8, a_sz);
            }
            if (!w32) {
                const __half* wp = wrow + (c + 1) * BKH;
#pragma unroll
                for (int j = 0; j < 2; ++j)
                    cp16(boff + CHH * 2u + j * 16u, wp + j * 8, 16u);
            }
            asm volatile("cp.async.commit_group;\n");
            asm volatile("cp.async.wait_group 1;\n");
        } else {
            asm volatile("cp.async.wait_group 0;\n");
        }
        __syncthreads();

        const __half* sA = smh + (c & 1) * (2 * CHH);
        const __half* sB = sA + CHH;
#pragma unroll
        for (int kk = 0; kk < BKH; kk += 16) {
            uint32_t afr[4][4];
            uint32_t bfr[4][2];
#pragma unroll
            for (int mt = 0; mt < 4; ++mt) {
                int ar = warp_m + mt * 16 + lg;
                afr[mt][0] = *(const uint32_t*)&sA[ar * PADH + kk + 2 * lt];
                afr[mt][1] = *(const uint32_t*)&sA[(ar + 8) * PADH + kk + 2 * lt];
                afr[mt][2] = *(const uint32_t*)&sA[ar * PADH + kk + 2 * lt + 8];
                afr[mt][3] = *(const uint32_t*)&sA[(ar + 8) * PADH + kk + 2 * lt + 8];
            }
#pragma unroll
            for (int nt = 0; nt < 4; ++nt) {
                int bn = warp_n + nt * 8 + lg;
                bfr[nt][0] = *(const uint32_t*)&sB[bn * PADH + kk + 2 * lt];
                bfr[nt][1] = *(const uint32_t*)&sB[bn * PADH + kk + 2 * lt + 8];
            }
#pragma unroll
            for (int mt = 0; mt < 4; ++mt) {
#pragma unroll
                for (int nt = 0; nt < 4; ++nt) {
                    asm volatile(
                        "mma.sync.aligned.m16n8k16.row.col.f32.f16.f16.f32 "
                        "{%0,%1,%2,%3}, {%4,%5,%6,%7}, {%8,%9}, {%0,%1,%2,%3};\n"
                        : "+f"(acc[mt][nt][0]), "+f"(acc[mt][nt][1]),
                          "+f"(acc[mt][nt][2]), "+f"(acc[mt][nt][3])
                        : "r"(afr[mt][0]), "r"(afr[mt][1]),
                          "r"(afr[mt][2]), "r"(afr[mt][3]),
                          "r"(bfr[nt][0]), "r"(bfr[nt][1]));
                }
            }
        }
        __syncthreads();
    }

    const bool do_relu = (flags & 2) != 0;
    const bool do_scale = (flags & 8) != 0;
#pragma unroll
    for (int mt = 0; mt < 4; ++mt) {
        int r0 = m0 + warp_m + mt * 16 + lg;
        int r1 = r0 + 8;
        float rs0 = 1.0f, rs1 = 1.0f;
        if (do_scale) {
            if (r0 < M) rs0 = rowscale[r0];
            if (r1 < M) rs1 = rowscale[r1];
        }
#pragma unroll
        for (int nt = 0; nt < 4; ++nt) {
            int cl = warp_n + nt * 8 + lt * 2;
            float b0 = sBias[cl], b1 = sBias[cl + 1];
            int col = n0 + cl;
            float v0 = acc[mt][nt][0] + b0;
            float v1 = acc[mt][nt][1] + b1;
            float v2 = acc[mt][nt][2] + b0;
            float v3 = acc[mt][nt][3] + b1;
            if (do_relu) {
                v0 = fmaxf(v0, 0.f); v1 = fmaxf(v1, 0.f);
                v2 = fmaxf(v2, 0.f); v3 = fmaxf(v3, 0.f);
            }
            v0 *= rs0; v1 *= rs0; v2 *= rs1; v3 *= rs1;
            if (r0 < M)
                *(__half2*)(C + (size_t)r0 * 256 + col) = __floats2half2_rn(v0, v1);
            if (r1 < M)
                *(__half2*)(C + (size_t)r1 * 256 + col) = __floats2half2_rn(v2, v3);
        }
    }
}

// ---------------- GCN aggregation: warp per node, x4 unroll -------------
// hs = h * dinv[row] (prescaled in GEMM epilogue).
// out[node] = relu(dinv[node] * (sum_src hs[src] + hs[node]) + bias)
__global__ void aggregate_kernel(const __half* __restrict__ hs,
                                 const float* __restrict__ bias,
                                 __half* __restrict__ out) {
    int node = (blockIdx.x * blockDim.x + threadIdx.x) >> 5;
    if (node >= NN) return;
    int lane = threadIdx.x & 31;
    const int co = lane * 8;                 // 8 halves per lane
    float acc[8];
#pragma unroll
    for (int i = 0; i < 8; ++i) acc[i] = 0.0f;

    int s = g_off[node], e = g_off[node + 1];
    int j = s;
    for (; j + 3 < e; j += 4) {
        int s0 = g_srcs[j], s1 = g_srcs[j + 1];
        int s2 = g_srcs[j + 2], s3 = g_srcs[j + 3];
        uint4 u0 = *(const uint4*)(hs + (size_t)s0 * 256 + co);
        uint4 u1 = *(const uint4*)(hs + (size_t)s1 * 256 + co);
        uint4 u2 = *(const uint4*)(hs + (size_t)s2 * 256 + co);
        uint4 u3 = *(const uint4*)(hs + (size_t)s3 * 256 + co);
        const __half2* p0 = (const __half2*)&u0;
        const __half2* p1 = (const __half2*)&u1;
        const __half2* p2 = (const __half2*)&u2;
        const __half2* p3 = (const __half2*)&u3;
#pragma unroll
        for (int q = 0; q < 4; ++q) {
            float2 f0 = __half22float2(p0[q]);
            float2 f1 = __half22float2(p1[q]);
            float2 f2 = __half22float2(p2[q]);
            float2 f3 = __half22float2(p3[q]);
            acc[q * 2 + 0] += (f0.x + f1.x) + (f2.x + f3.x);
            acc[q * 2 + 1] += (f0.y + f1.y) + (f2.y + f3.y);
        }
    }
    for (; j < e; ++j) {
        int s0 = g_srcs[j];
        uint4 u0 = *(const uint4*)(hs + (size_t)s0 * 256 + co);
        const __half2* p0 = (const __half2*)&u0;
#pragma unroll
        for (int q = 0; q < 4; ++q) {
            float2 f0 = __half22float2(p0[q]);
            acc[q * 2 + 0] += f0.x;
            acc[q * 2 + 1] += f0.y;
        }
    }

    float di = g_dinv[node];
    uint4 us = *(const uint4*)(hs + (size_t)node * 256 + co);
    const __half2* ps = (const __half2*)&us;
    float4 b0 = *(const float4*)(bias + co);
    float4 b1 = *(const float4*)(bias + co + 4);
    const float bb[8] = {b0.x, b0.y, b0.z, b0.w, b1.x, b1.y, b1.z, b1.w};
    __half2 o[4];
#pragma unroll
    for (int q = 0; q < 4; ++q) {
        float2 fs = __half22float2(ps[q]);
        float v0 = fmaxf(di * (acc[q * 2 + 0] + fs.x) + bb[q * 2 + 0], 0.0f);
        float v1 = fmaxf(di * (acc[q * 2 + 1] + fs.y) + bb[q * 2 + 1], 0.0f);
        o[q] = __floats2half2_rn(v0, v1);
    }
    *(uint4*)(out + (size_t)node * 256 + co) = *(const uint4*)o;
}

// ---------------- pooling ----------------
__global__ void k_gstart(const int* __restrict__ batch) {
    int i = blockIdx.x * blockDim.x + threadIdx.x;
    if (i >= NN) return;
    int b = batch[i];
    int prev = (i == 0) ? -1 : batch[i - 1];
    for (int g = prev + 1; g <= b; ++g) g_gstart[g] = i;
    if (i == NN - 1) {
        for (int g = b + 1; g <= GG; ++g) g_gstart[g] = NN;
    }
}
__global__ void k_pool(const __half* __restrict__ h, __half* __restrict__ out) {
    int warp = (blockIdx.x * blockDim.x + threadIdx.x) >> 5;
    if (warp >= GG) return;
    int lane = threadIdx.x & 31;
    const int co = lane * 8;
    float acc[8];
#pragma unroll
    for (int i = 0; i < 8; ++i) acc[i] = 0.0f;
    int s = g_gstart[warp], e = g_gstart[warp + 1];
    for (int i = s; i < e; ++i) {
        uint4 u = *(const uint4*)(h + (size_t)i * 256 + co);
        const __half2* p = (const __half2*)&u;
#pragma unroll
        for (int q = 0; q < 4; ++q) {
            float2 f = __half22float2(p[q]);
            acc[q * 2 + 0] += f.x;
            acc[q * 2 + 1] += f.y;
        }
    }
    __half2 o[4];
#pragma unroll
    for (int q = 0; q < 4; ++q)
        o[q] = __floats2half2_rn(acc[q * 2 + 0], acc[q * 2 + 1]);
    *(uint4*)(out + (size_t)warp * 256 + co) = *(const uint4*)o;
}

// ---------------- output head ----------------
__global__ void k_out(const __half* __restrict__ g,
                      const float* __restrict__ out_w,
                      const float* __restrict__ out_b,
                      float* __restrict__ out) {
    int warp = (blockIdx.x * blockDim.x + threadIdx.x) >> 5;
    if (warp >= GG) return;
    int lane = threadIdx.x & 31;
    const int co = lane * 8;
    uint4 u = *(const uint4*)(g + (size_t)warp * 256 + co);
    const __half2* p = (const __half2*)&u;
    float p0 = 0.f, p1 = 0.f;
#pragma unroll
    for (int q = 0; q < 4; ++q) {
        float2 f = __half22float2(p[q]);
        p0 += f.x * out_w[co + q * 2] + f.y * out_w[co + q * 2 + 1];
        p1 += f.x * out_w[256 + co + q * 2] + f.y * out_w[256 + co + q * 2 + 1];
    }
#pragma unroll
    for (int o = 16; o; o >>= 1) {
        p0 += __shfl_down_sync(0xffffffffu, p0, o);
        p1 += __shfl_down_sync(0xffffffffu, p1, o);
    }
    if (lane == 0) {
        float z0 = p0 + out_b[0];
        float z1 = p1 + out_b[1];
        float m = fmaxf(z0, z1);
        float lse = m + logf(expf(z0 - m) + expf(z1 - m));
        out[warp * 2 + 0] = z0 - lse;
        out[warp * 2 + 1] = z1 - lse;
    }
}

// ---------------- launch ----------------
extern "C" void kernel_launch(void* const* d_in, const int* in_sizes, int n_in,
                              void* d_out, int out_size) {
    const float* x       = (const float*)d_in[0];
    const int*   ei      = (const int*)d_in[1];
    const int*   batch   = (const int*)d_in[2];
    const float* W_embed = (const float*)d_in[3];
    const float* b_embed = (const float*)d_in[4];
    const float* conv_w  = (const float*)d_in[5];
    const float* conv_b  = (const float*)d_in[6];
    const float* fc_w    = (const float*)d_in[7];
    const float* fc_b    = (const float*)d_in[8];
    const float* out_w   = (const float*)d_in[9];
    const float* out_b   = (const float*)d_in[10];
    float* out = (float*)d_out;

    __half *bufA, *bufB, *bufC, *wconv, *wfc, *gA, *gB;
    float* dinv;
    cudaGetSymbolAddress((void**)&bufA, g_bufA);
    cudaGetSymbolAddress((void**)&bufB, g_bufB);
    cudaGetSymbolAddress((void**)&bufC, g_bufC);
    cudaGetSymbolAddress((void**)&wconv, g_wconv);
    cudaGetSymbolAddress((void**)&wfc, g_wfc);
    cudaGetSymbolAddress((void**)&gA, g_gA);
    cudaGetSymbolAddress((void**)&gB, g_gB);
    cudaGetSymbolAddress((void**)&dinv, g_dinv);

    static bool init_done = false;
    static cudaStream_t s2;
    static cudaEvent_t evFork, evDinv, evCSR;
    if (!init_done) {
        cudaFuncSetAttribute(gemm_f16_kernel,
                             cudaFuncAttributeMaxDynamicSharedMemorySize,
                             4 * CHH * (int)sizeof(__half));
        cudaStreamCreateWithFlags(&s2, cudaStreamNonBlocking);
        cudaEventCreateWithFlags(&evFork, cudaEventDisableTiming);
        cudaEventCreateWithFlags(&evDinv, cudaEventDisableTiming);
        cudaEventCreateWithFlags(&evCSR, cudaEventDisableTiming);
        init_done = true;
    }
    const int GEMM_SMEM = 4 * CHH * (int)sizeof(__half);  // 40960
    const int TB = 256;
    const int AGG_GRID = (NN * 32 + TB - 1) / TB;
    dim3 gridFull((NN + 127) / 128, 2);
    dim3 gridG((GG + 127) / 128, 2);

    cudaEventRecord(evFork, 0);
    cudaStreamWaitEvent(s2, evFork, 0);

    // --- R14 topology, with scan2 fused into scan3 ---
    // [1] convert conv weights (s0)
    k_h16<<<(3 * HH * HH + TB - 1) / TB, TB>>>(conv_w, wconv, 3 * HH * HH);
    // [2] embed GEMM: both A and W read fp32-direct (stride 59)
    gemm_f16_kernel<<<gridFull, 256, GEMM_SMEM>>>(
        nullptr, x, nullptr, W_embed, b_embed, nullptr, bufA,
        NN, KPAD, 3 | 16 | 32);
    // CSR front half on s2 (scan1 produces dinv)
    k_zero_deg<<<(NN + TB - 1) / TB, TB, 0, s2>>>();
    k_hist<<<(EE + TB - 1) / TB, TB, 0, s2>>>(ei);
    k_scan1<<<SCAN_NB, SCAN_B, 0, s2>>>();
    cudaEventRecord(evDinv, s2);
    // conv1 GEMM (s0) — waits on dinv
    cudaStreamWaitEvent(0, evDinv, 0);
    gemm_f16_kernel<<<gridFull, 256, GEMM_SMEM>>>(
        bufA, nullptr, wconv, nullptr, nullptr, dinv, bufB, NN, HH, 8);
    // rest of CSR chain + gstart + fc convert on s2 (all before evCSR,
    // so nothing runs concurrently with the aggregates)
    k_scan3<<<SCAN_NB, SCAN_B, 0, s2>>>();
    k_scatter<<<(EE + TB - 1) / TB, TB, 0, s2>>>(ei);
    k_gstart<<<(NN + TB - 1) / TB, TB, 0, s2>>>(batch);
    k_h16<<<(3 * HH * HH + TB - 1) / TB, TB, 0, s2>>>(fc_w, wfc, 3 * HH * HH);
    cudaEventRecord(evCSR, s2);
    cudaStreamWaitEvent(0, evCSR, 0);   // aggregates need full CSR

    // ---- conv layers (serial G->A; conv1 GEMM already issued) ----
    __half* act[4] = {bufA, bufC, bufA, bufC};
    aggregate_kernel<<<AGG_GRID, TB>>>(bufB, conv_b, act[1]);
    for (int i = 1; i < 3; ++i) {
        gemm_f16_kernel<<<gridFull, 256, GEMM_SMEM>>>(
            act[i], nullptr, wconv + (size_t)i * HH * HH, nullptr, nullptr,
            dinv, bufB, NN, HH, 8);
        aggregate_kernel<<<AGG_GRID, TB>>>(bufB, conv_b + (size_t)i * HH,
                                           act[i + 1]);
    }

    // ---- global_add_pool (final activations in bufC) ----
    k_pool<<<(GG * 32) / TB, TB>>>(bufC, gA);

    // ---- FC stack ----
    gemm_f16_kernel<<<gridG, 256, GEMM_SMEM>>>(gA, nullptr, wfc, nullptr,
                                               fc_b, nullptr, gB, GG, HH, 3);
    gemm_f16_kernel<<<gridG, 256, GEMM_SMEM>>>(gB, nullptr, wfc + HH * HH,
                                               nullptr, fc_b + HH, nullptr,
                                               gA, GG, HH, 3);
    gemm_f16_kernel<<<gridG, 256, GEMM_SMEM>>>(gA, nullptr, wfc + 2 * HH * HH,
                                               nullptr, fc_b + 2 * HH, nullptr,
                                               gB, GG, HH, 3);

    // ---- output + log_softmax ----
    k_out<<<(GG * 32) / TB, TB>>>(gB, out_w, out_b, out);
}